// round 2
// baseline (speedup 1.0000x reference)
#include <cuda_runtime.h>
#include <cstdint>

#define OBS_DIMV 4096
#define NGVF     4096
#define IPG      16
#define HPG      8
#define NA       18
#define TF       36864
#define ROWS     8
#define THREADS  256
#define CHUNK    32
#define NCHUNK   (NGVF / CHUNK)   /* 128 */

/* padded smem strides (floats / ints) for conflict-free access */
#define OSTRIDE  4100
#define WSTRIDE  132
#define QSTRIDE  148
#define ISTRIDE  20

/* float-offsets within dynamic smem */
#define OBS_OFF  0
#define OBS_SZ   (ROWS * OSTRIDE)          /* 32800 */
#define W_OFF    (OBS_OFF + OBS_SZ)
#define W_SZ     (CHUNK * WSTRIDE)         /* 4224  */
#define Q_OFF    (W_OFF + 2 * W_SZ)
#define Q_SZ     (CHUNK * QSTRIDE)         /* 4736  */
#define I_OFF    (Q_OFF + 2 * Q_SZ)
#define I_SZ     (CHUNK * ISTRIDE)         /* 640   */
#define P_OFF    (I_OFF + 2 * I_SZ)
#define P_SZ     (9 * ROWS * NA)           /* 1296  */
#define SMEM_FLOATS (P_OFF + P_SZ)
#define SMEM_BYTES  (SMEM_FLOATS * 4)      /* 213184 bytes */

__device__ __forceinline__ void cp16(uint32_t dst, const void* src) {
    asm volatile("cp.async.cg.shared.global [%0], [%1], 16;\n" :: "r"(dst), "l"(src));
}
__device__ __forceinline__ void cp_commit() {
    asm volatile("cp.async.commit_group;\n");
}
template <int N>
__device__ __forceinline__ void cp_wait() {
    asm volatile("cp.async.wait_group %0;\n" :: "n"(N));
}

__device__ __forceinline__ void stage_chunk(int c, int buf, uint32_t sbase,
                                            const float* __restrict__ gvfW,
                                            const float* __restrict__ qW,
                                            const int*   __restrict__ gidx,
                                            int tid)
{
    uint32_t wdst = sbase + (uint32_t)(W_OFF + buf * W_SZ) * 4u;
    uint32_t qdst = sbase + (uint32_t)(Q_OFF + buf * Q_SZ) * 4u;
    uint32_t idst = sbase + (uint32_t)(I_OFF + buf * I_SZ) * 4u;
    const float* wsrc = gvfW + (size_t)c * CHUNK * (HPG * IPG);
    const int*   isrc = gidx + (size_t)c * CHUNK * IPG;

    /* gvf_W chunk: 32 gvfs x 128 floats = 1024 float4 ops */
    #pragma unroll
    for (int k = 0; k < 4; ++k) {
        int id = tid + k * THREADS;
        int g  = id >> 5;
        int j  = id & 31;
        cp16(wdst + (uint32_t)(g * WSTRIDE + j * 4) * 4u, wsrc + g * 128 + j * 4);
    }
    /* idx chunk: 32 gvfs x 16 ints = 128 float4 ops */
    if (tid < 128) {
        int g = tid >> 2;
        int j = tid & 3;
        cp16(idst + (uint32_t)(g * ISTRIDE + j * 4) * 4u, isrc + g * 16 + j * 4);
    }
    /* q_W gvf-columns chunk: 32 gvfs x 18 actions x 8 = 1152 float4 ops */
    #pragma unroll
    for (int k = 0; k < 5; ++k) {
        int id = tid + k * THREADS;
        if (id < 1152) {
            int g   = id / 36;
            int rem = id - g * 36;
            int a   = rem >> 1;
            int h4  = rem & 1;
            cp16(qdst + (uint32_t)(g * QSTRIDE + a * 8 + h4 * 4) * 4u,
                 qW + (size_t)a * TF + OBS_DIMV + (size_t)(c * CHUNK + g) * HPG + h4 * 4);
        }
    }
}

extern __shared__ float smf[];

__global__ void __launch_bounds__(THREADS, 1)
nibbler_fused_kernel(const float* __restrict__ obs,
                     const float* __restrict__ gvfW,
                     const float* __restrict__ qW,
                     const int*   __restrict__ gidx,
                     float*       __restrict__ out)
{
    const int tid  = threadIdx.x;
    const int w    = tid >> 5;
    const int lane = tid & 31;
    const int r0   = blockIdx.x * ROWS;

    uint32_t sbase = (uint32_t)__cvta_generic_to_shared(smf);

    /* kick off chunk-0 weight staging first so it overlaps the obs staging */
    stage_chunk(0, 0, sbase, gvfW, qW, gidx, tid);
    cp_commit();

    /* stage 8 obs rows into smem (fp32, float4, padded stride) */
    for (int id = tid; id < ROWS * (OBS_DIMV / 4); id += THREADS) {
        int p = id >> 10;          /* /1024 */
        int j = id & 1023;
        float4 v = *(const float4*)(obs + (size_t)(r0 + p) * OBS_DIMV + j * 4);
        *(float4*)(smf + p * OSTRIDE + j * 4) = v;
    }

    float acc[NA];
    #pragma unroll
    for (int a = 0; a < NA; ++a) acc[a] = 0.f;

    const int gq = lane & 3;   /* gvf slot within warp   */
    const int r  = lane >> 2;  /* row within CTA (0..7)  */
    const float* orow = smf + r * OSTRIDE;

    #pragma unroll 1
    for (int c = 0; c < NCHUNK; ++c) {
        if (c + 1 < NCHUNK) {
            stage_chunk(c + 1, (c + 1) & 1, sbase, gvfW, qW, gidx, tid);
            cp_commit();
            cp_wait<1>();
        } else {
            cp_wait<0>();
        }
        __syncthreads();

        const int buf = c & 1;
        const int gl  = w * 4 + gq;            /* gvf index within chunk */
        const float* Wg = smf + W_OFF + buf * W_SZ + gl * WSTRIDE;
        const float* Qg = smf + Q_OFF + buf * Q_SZ + gl * QSTRIDE;
        const int*   Ig = (const int*)(smf + I_OFF + buf * I_SZ) + gl * ISTRIDE;

        /* gather 16 random obs columns for (row r, gvf gl) */
        float x[IPG];
        #pragma unroll
        for (int i = 0; i < IPG; ++i) x[i] = orow[Ig[i]];

        /* hidden: 8 units x 16 inputs, then ReLU */
        float f[HPG];
        #pragma unroll
        for (int h = 0; h < HPG; ++h) {
            float4 w0 = *(const float4*)(Wg + h * 16);
            float4 w1 = *(const float4*)(Wg + h * 16 + 4);
            float4 w2 = *(const float4*)(Wg + h * 16 + 8);
            float4 w3 = *(const float4*)(Wg + h * 16 + 12);
            float s = x[0]  * w0.x + x[1]  * w0.y + x[2]  * w0.z + x[3]  * w0.w
                    + x[4]  * w1.x + x[5]  * w1.y + x[6]  * w1.z + x[7]  * w1.w
                    + x[8]  * w2.x + x[9]  * w2.y + x[10] * w2.z + x[11] * w2.w
                    + x[12] * w3.x + x[13] * w3.y + x[14] * w3.z + x[15] * w3.w;
            f[h] = fmaxf(s, 0.f);
        }

        /* Q-head contribution of this gvf's 8 features */
        #pragma unroll
        for (int a = 0; a < NA; ++a) {
            float4 qa = *(const float4*)(Qg + a * 8);
            float4 qb = *(const float4*)(Qg + a * 8 + 4);
            acc[a] += f[0] * qa.x + f[1] * qa.y + f[2] * qa.z + f[3] * qa.w
                    + f[4] * qb.x + f[5] * qb.y + f[6] * qb.z + f[7] * qb.w;
        }
        __syncthreads();   /* buf must be fully read before it is re-staged */
    }

    /* reduce the 4 gvf-slots of each row within the warp (deterministic) */
    #pragma unroll
    for (int a = 0; a < NA; ++a) {
        acc[a] += __shfl_xor_sync(0xffffffffu, acc[a], 1);
        acc[a] += __shfl_xor_sync(0xffffffffu, acc[a], 2);
    }
    if (gq == 0) {
        float* P = smf + P_OFF + (w * ROWS + r) * NA;
        #pragma unroll
        for (int a = 0; a < NA; ++a) P[a] = acc[a];
    }

    /* obs-direct part of Q: warp w handles batch row w */
    {
        float oa[NA];
        #pragma unroll
        for (int a = 0; a < NA; ++a) oa[a] = 0.f;
        const float* ro = smf + w * OSTRIDE;
        #pragma unroll 4
        for (int j = lane; j < OBS_DIMV / 4; j += 32) {
            float4 ov = *(const float4*)(ro + j * 4);
            #pragma unroll
            for (int a = 0; a < NA; ++a) {
                float4 qv = *(const float4*)(qW + (size_t)a * TF + j * 4);
                oa[a] += ov.x * qv.x + ov.y * qv.y + ov.z * qv.z + ov.w * qv.w;
            }
        }
        #pragma unroll
        for (int a = 0; a < NA; ++a) {
            oa[a] += __shfl_xor_sync(0xffffffffu, oa[a], 16);
            oa[a] += __shfl_xor_sync(0xffffffffu, oa[a], 8);
            oa[a] += __shfl_xor_sync(0xffffffffu, oa[a], 4);
            oa[a] += __shfl_xor_sync(0xffffffffu, oa[a], 2);
            oa[a] += __shfl_xor_sync(0xffffffffu, oa[a], 1);
        }
        if (lane == 0) {
            float* P = smf + P_OFF + (8 * ROWS + w) * NA;
            #pragma unroll
            for (int a = 0; a < NA; ++a) P[a] = oa[a];
        }
    }
    __syncthreads();

    /* final: 144 threads sum 9 partials each and write out */
    if (tid < ROWS * NA) {
        int rr = tid / NA;
        int a  = tid - rr * NA;
        float s = 0.f;
        #pragma unroll
        for (int p = 0; p < 8; ++p) s += smf[P_OFF + (p * ROWS + rr) * NA + a];
        s += smf[P_OFF + (8 * ROWS + rr) * NA + a];
        out[(size_t)(r0 + rr) * NA + a] = s;
    }
}

extern "C" void kernel_launch(void* const* d_in, const int* in_sizes, int n_in,
                              void* d_out, int out_size)
{
    const float* obs  = (const float*)d_in[0];
    const float* gvfW = (const float*)d_in[1];
    const float* qW   = (const float*)d_in[2];
    const int*   gidx = (const int*)d_in[3];
    float* out = (float*)d_out;

    cudaFuncSetAttribute(nibbler_fused_kernel,
                         cudaFuncAttributeMaxDynamicSharedMemorySize, SMEM_BYTES);
    nibbler_fused_kernel<<<2048 / ROWS, THREADS, SMEM_BYTES>>>(obs, gvfW, qW, gidx, out);
}

// round 3
// speedup vs baseline: 1.7527x; 1.7527x over previous
#include <cuda_runtime.h>
#include <cuda_fp16.h>
#include <cstdint>

#define OBS_DIMV 4096
#define NGVF     4096
#define IPG      16
#define HPG      8
#define NA       18
#define TF       36864
#define ROWS     16
#define PAIRS    8
#define THREADS  512
#define CHUNK    32
#define NCHUNK   (NGVF / CHUNK)   /* 128 */

/* smem strides */
#define OSTRIDE_H2 4100           /* half2 per pair row (4096 + pad, 16B aligned) */
#define WSTRIDE  132
#define QSTRIDE  148
#define ISTRIDE  20

/* float-offsets within dynamic smem */
#define OBS_FL   (PAIRS * OSTRIDE_H2)      /* 32800 floats of half2 storage */
#define W_OFF    OBS_FL                    /* 32800 */
#define W_SZ     (CHUNK * WSTRIDE)         /* 4224  */
#define Q_OFF    (W_OFF + 2 * W_SZ)        /* 41248 */
#define Q_SZ     (CHUNK * QSTRIDE)         /* 4736  */
#define I_OFF    (Q_OFF + 2 * Q_SZ)        /* 50720 */
#define I_SZ     (CHUNK * ISTRIDE)         /* 640   */
#define P_OFF    (I_OFF + 2 * I_SZ)        /* 52000 */
#define P_SZ     (17 * ROWS * NA)          /* 4896  */
#define SMEM_FLOATS (P_OFF + P_SZ)         /* 56896 */
#define SMEM_BYTES  (SMEM_FLOATS * 4)      /* 227584 B <= 232448 */

__device__ __forceinline__ void cp16(uint32_t dst, const void* src) {
    asm volatile("cp.async.cg.shared.global [%0], [%1], 16;\n" :: "r"(dst), "l"(src));
}
__device__ __forceinline__ void cp_commit() {
    asm volatile("cp.async.commit_group;\n");
}
template <int N>
__device__ __forceinline__ void cp_wait() {
    asm volatile("cp.async.wait_group %0;\n" :: "n"(N));
}

__device__ __forceinline__ void stage_chunk(int c, int buf, uint32_t sbase,
                                            const float* __restrict__ gvfW,
                                            const float* __restrict__ qW,
                                            const int*   __restrict__ gidx,
                                            int tid)
{
    uint32_t wdst = sbase + (uint32_t)(W_OFF + buf * W_SZ) * 4u;
    uint32_t qdst = sbase + (uint32_t)(Q_OFF + buf * Q_SZ) * 4u;
    uint32_t idst = sbase + (uint32_t)(I_OFF + buf * I_SZ) * 4u;
    const float* wsrc = gvfW + (size_t)c * CHUNK * (HPG * IPG);
    const int*   isrc = gidx + (size_t)c * CHUNK * IPG;

    /* gvf_W chunk: 32 gvfs x 128 floats = 1024 float4 */
    #pragma unroll
    for (int k = 0; k < 2; ++k) {
        int id = tid + k * THREADS;
        int g  = id >> 5;
        int j  = id & 31;
        cp16(wdst + (uint32_t)(g * WSTRIDE + j * 4) * 4u, wsrc + g * 128 + j * 4);
    }
    /* idx chunk: 32 gvfs x 16 ints = 128 int4 */
    if (tid < 128) {
        int g = tid >> 2;
        int j = tid & 3;
        cp16(idst + (uint32_t)(g * ISTRIDE + j * 4) * 4u, isrc + g * 16 + j * 4);
    }
    /* q_W gvf-columns chunk: 32 gvfs x 18 actions x 2 float4 = 1152 */
    #pragma unroll
    for (int k = 0; k < 3; ++k) {
        int id = tid + k * THREADS;
        if (id < 1152) {
            int g   = id / 36;
            int rem = id - g * 36;
            int a   = rem >> 1;
            int h4  = rem & 1;
            cp16(qdst + (uint32_t)(g * QSTRIDE + a * 8 + h4 * 4) * 4u,
                 qW + (size_t)a * TF + OBS_DIMV + (size_t)(c * CHUNK + g) * HPG + h4 * 4);
        }
    }
}

extern __shared__ float smf[];

__global__ void __launch_bounds__(THREADS, 1)
nibbler_fused_kernel(const float* __restrict__ obs,
                     const float* __restrict__ gvfW,
                     const float* __restrict__ qW,
                     const int*   __restrict__ gidx,
                     float*       __restrict__ out)
{
    const int tid  = threadIdx.x;
    const int w    = tid >> 5;     /* 0..15 */
    const int lane = tid & 31;
    const int r0   = blockIdx.x * ROWS;

    uint32_t sbase = (uint32_t)__cvta_generic_to_shared(smf);

    /* kick off chunk-0 weight staging so it overlaps obs staging */
    stage_chunk(0, 0, sbase, gvfW, qW, gidx, tid);
    cp_commit();

    /* stage 16 obs rows into smem as fp16 half2 row-pairs */
    {
        __half2* sObs = reinterpret_cast<__half2*>(smf);
        for (int id = tid; id < PAIRS * (OBS_DIMV / 4); id += THREADS) {
            int p = id >> 10;          /* pair 0..7 */
            int j = id & 1023;         /* float4 index in row */
            float4 va = *(const float4*)(obs + (size_t)(r0 + 2 * p    ) * OBS_DIMV + j * 4);
            float4 vb = *(const float4*)(obs + (size_t)(r0 + 2 * p + 1) * OBS_DIMV + j * 4);
            __half2 h0 = __floats2half2_rn(va.x, vb.x);
            __half2 h1 = __floats2half2_rn(va.y, vb.y);
            __half2 h2 = __floats2half2_rn(va.z, vb.z);
            __half2 h3 = __floats2half2_rn(va.w, vb.w);
            uint4 pk;
            pk.x = *(uint32_t*)&h0; pk.y = *(uint32_t*)&h1;
            pk.z = *(uint32_t*)&h2; pk.w = *(uint32_t*)&h3;
            *(uint4*)(sObs + p * OSTRIDE_H2 + j * 4) = pk;
        }
    }

    /* compute-phase mapping: thread = (gvf slot, row) */
    const int gvfslot = lane & 1;        /* 0..1 */
    const int row     = lane >> 1;       /* 0..15 */
    const int pair    = row >> 1;
    const int rowhalf = row & 1;
    const int gl      = w * 2 + gvfslot; /* gvf in chunk 0..31 */
    const __half* oph = reinterpret_cast<const __half*>(smf)
                        + pair * (OSTRIDE_H2 * 2) + rowhalf;

    float acc[NA];
    #pragma unroll
    for (int a = 0; a < NA; ++a) acc[a] = 0.f;

    #pragma unroll 1
    for (int c = 0; c < NCHUNK; ++c) {
        if (c + 1 < NCHUNK) {
            stage_chunk(c + 1, (c + 1) & 1, sbase, gvfW, qW, gidx, tid);
            cp_commit();
            cp_wait<1>();
        } else {
            cp_wait<0>();
        }
        __syncthreads();

        const int buf = c & 1;
        const float* Wg = smf + W_OFF + buf * W_SZ + gl * WSTRIDE;
        const float* Qg = smf + Q_OFF + buf * Q_SZ + gl * QSTRIDE;
        const int4*  I4 = (const int4*)((const int*)(smf + I_OFF + buf * I_SZ) + gl * ISTRIDE);

        int4 i0 = I4[0], i1 = I4[1], i2 = I4[2], i3 = I4[3];
        float x[IPG];
        x[0]  = __half2float(oph[i0.x * 2]);
        x[1]  = __half2float(oph[i0.y * 2]);
        x[2]  = __half2float(oph[i0.z * 2]);
        x[3]  = __half2float(oph[i0.w * 2]);
        x[4]  = __half2float(oph[i1.x * 2]);
        x[5]  = __half2float(oph[i1.y * 2]);
        x[6]  = __half2float(oph[i1.z * 2]);
        x[7]  = __half2float(oph[i1.w * 2]);
        x[8]  = __half2float(oph[i2.x * 2]);
        x[9]  = __half2float(oph[i2.y * 2]);
        x[10] = __half2float(oph[i2.z * 2]);
        x[11] = __half2float(oph[i2.w * 2]);
        x[12] = __half2float(oph[i3.x * 2]);
        x[13] = __half2float(oph[i3.y * 2]);
        x[14] = __half2float(oph[i3.z * 2]);
        x[15] = __half2float(oph[i3.w * 2]);

        /* hidden: 8 units x 16 inputs, ReLU */
        float f[HPG];
        #pragma unroll
        for (int h = 0; h < HPG; ++h) {
            float4 w0 = *(const float4*)(Wg + h * 16);
            float4 w1 = *(const float4*)(Wg + h * 16 + 4);
            float4 w2 = *(const float4*)(Wg + h * 16 + 8);
            float4 w3 = *(const float4*)(Wg + h * 16 + 12);
            float s = x[0]  * w0.x + x[1]  * w0.y + x[2]  * w0.z + x[3]  * w0.w
                    + x[4]  * w1.x + x[5]  * w1.y + x[6]  * w1.z + x[7]  * w1.w
                    + x[8]  * w2.x + x[9]  * w2.y + x[10] * w2.z + x[11] * w2.w
                    + x[12] * w3.x + x[13] * w3.y + x[14] * w3.z + x[15] * w3.w;
            f[h] = fmaxf(s, 0.f);
        }

        /* Q-head contribution of this gvf's 8 features */
        #pragma unroll
        for (int a = 0; a < NA; ++a) {
            float4 qa = *(const float4*)(Qg + a * 8);
            float4 qb = *(const float4*)(Qg + a * 8 + 4);
            acc[a] += f[0] * qa.x + f[1] * qa.y + f[2] * qa.z + f[3] * qa.w
                    + f[4] * qb.x + f[5] * qb.y + f[6] * qb.z + f[7] * qb.w;
        }
        __syncthreads();
    }

    /* reduce 2 gvf-slots per row within warp (deterministic) */
    #pragma unroll
    for (int a = 0; a < NA; ++a)
        acc[a] += __shfl_xor_sync(0xffffffffu, acc[a], 1);
    if (gvfslot == 0) {
        float* P = smf + P_OFF + (w * ROWS + row) * NA;
        #pragma unroll
        for (int a = 0; a < NA; ++a) P[a] = acc[a];
    }

    /* obs-direct part of Q: warp w handles row w, fp32 straight from gmem */
    {
        float oa[NA];
        #pragma unroll
        for (int a = 0; a < NA; ++a) oa[a] = 0.f;
        const float* ro = obs + (size_t)(r0 + w) * OBS_DIMV;
        #pragma unroll 4
        for (int j = lane; j < OBS_DIMV / 4; j += 32) {
            float4 ov = *(const float4*)(ro + j * 4);
            #pragma unroll
            for (int a = 0; a < NA; ++a) {
                float4 qv = *(const float4*)(qW + (size_t)a * TF + j * 4);
                oa[a] += ov.x * qv.x + ov.y * qv.y + ov.z * qv.z + ov.w * qv.w;
            }
        }
        #pragma unroll
        for (int a = 0; a < NA; ++a) {
            oa[a] += __shfl_xor_sync(0xffffffffu, oa[a], 16);
            oa[a] += __shfl_xor_sync(0xffffffffu, oa[a], 8);
            oa[a] += __shfl_xor_sync(0xffffffffu, oa[a], 4);
            oa[a] += __shfl_xor_sync(0xffffffffu, oa[a], 2);
            oa[a] += __shfl_xor_sync(0xffffffffu, oa[a], 1);
        }
        if (lane == 0) {
            float* P = smf + P_OFF + (16 * ROWS + w) * NA;
            #pragma unroll
            for (int a = 0; a < NA; ++a) P[a] = oa[a];
        }
    }
    __syncthreads();

    /* final: 288 threads sum 17 partials each and write */
    if (tid < ROWS * NA) {
        int rr = tid / NA;
        int a  = tid - rr * NA;
        float s = 0.f;
        #pragma unroll
        for (int p = 0; p < 16; ++p) s += smf[P_OFF + (p * ROWS + rr) * NA + a];
        s += smf[P_OFF + (16 * ROWS + rr) * NA + a];
        out[(size_t)(r0 + rr) * NA + a] = s;
    }
}

extern "C" void kernel_launch(void* const* d_in, const int* in_sizes, int n_in,
                              void* d_out, int out_size)
{
    const float* obs  = (const float*)d_in[0];
    const float* gvfW = (const float*)d_in[1];
    const float* qW   = (const float*)d_in[2];
    const int*   gidx = (const int*)d_in[3];
    float* out = (float*)d_out;

    cudaFuncSetAttribute(nibbler_fused_kernel,
                         cudaFuncAttributeMaxDynamicSharedMemorySize, SMEM_BYTES);
    nibbler_fused_kernel<<<2048 / ROWS, THREADS, SMEM_BYTES>>>(obs, gvfW, qW, gidx, out);
}